// round 12
// baseline (speedup 1.0000x reference)
#include <cuda_runtime.h>
#include <cuda_bf16.h>
#include <cuda_fp16.h>
#include <cstdint>

// Problem constants (fixed by the dataset)
#define DHEAD 128
#define MPROJ 128
#define NQ    4096
#define NK    8192
#define SCALE_CONST 0.009791516698f  // sqrt(pi/2)/128

// ---------------- device-global scratch (pre-swizzled SW128 slab layout) -------
// g_q / g_signs: fp16, 128-row tiles of 32KB; two 16KB slabs (64 cols each);
//                slab offset = sw128(row*128 + col*2).
__device__ __half g_signs[NK * MPROJ];
__device__ float  g_nscale[NK];
__device__ __half g_q[NQ * MPROJ];

__device__ __forceinline__ uint32_t sw128(uint32_t x) { return x ^ ((x >> 3) & 0x70); }

// ================================================================================
// Prep: fp32 GEMM rows @ S^T, smem-free (all operands via __ldg; S is L1/L2-hot).
// 32 rows/block, 128 threads, 4 rows x 8 cols per thread. FMA k-order identical
// to prior passing rounds (sign decisions are boundary-sensitive).
//   blocks [0,256): residual -> signs (fp16 ±1, swizzled) + nscale
//   blocks [256,384): query  -> q_proj (fp16, swizzled)
// ================================================================================
#define PREP_ROWS 32
#define PREP_THREADS 128

__global__ __launch_bounds__(PREP_THREADS)
void qjl_prep_kernel(const float* __restrict__ query,
                     const float* __restrict__ residual,
                     const float* __restrict__ S)
{
    const int tid = threadIdx.x;
    const bool is_res = (blockIdx.x < (NK / PREP_ROWS));
    const int rbase = is_res ? blockIdx.x * PREP_ROWS
                             : (blockIdx.x - NK / PREP_ROWS) * PREP_ROWS;
    const float* src = is_res ? residual : query;

    const int rg = tid & 7;    // 4 rows: 4*rg .. 4*rg+3
    const int cg = tid >> 3;   // 8 cols: 8*cg .. 8*cg+7

    const float4* arows = (const float4*)(src + (size_t)(rbase + 4 * rg) * DHEAD);
    const float4* brows = (const float4*)(S + (size_t)(8 * cg) * DHEAD);

    float acc[4][8];
    #pragma unroll
    for (int i = 0; i < 4; i++)
        #pragma unroll
        for (int j = 0; j < 8; j++) acc[i][j] = 0.f;

    #pragma unroll 4
    for (int k4 = 0; k4 < 32; k4++) {
        float4 a[4], b[8];
        #pragma unroll
        for (int i = 0; i < 4; i++) a[i] = __ldg(arows + i * 32 + k4);
        #pragma unroll
        for (int j = 0; j < 8; j++) b[j] = __ldg(brows + j * 32 + k4);
        #pragma unroll
        for (int j = 0; j < 8; j++) {
            #pragma unroll
            for (int i = 0; i < 4; i++) {
                acc[i][j] = fmaf(a[i].x, b[j].x, acc[i][j]);
                acc[i][j] = fmaf(a[i].y, b[j].y, acc[i][j]);
                acc[i][j] = fmaf(a[i].z, b[j].z, acc[i][j]);
                acc[i][j] = fmaf(a[i].w, b[j].w, acc[i][j]);
            }
        }
    }

    const int col8 = 8 * cg;              // col base (0..120)
    if (is_res) {
        #pragma unroll
        for (int i = 0; i < 4; i++) {
            union { __half h[8]; uint4 u; } pk;
            #pragma unroll
            for (int j = 0; j < 8; j++)
                pk.h[j] = __float2half(acc[i][j] >= 0.f ? 1.f : -1.f);
            int row = rbase + 4 * rg + i;
            uint32_t off = (uint32_t)(row >> 7) * 32768u
                         + (uint32_t)(col8 >> 6) * 16384u
                         + sw128((uint32_t)(row & 127) * 128u + (uint32_t)(col8 & 63) * 2u);
            *(uint4*)((char*)g_signs + off) = pk.u;
        }
        // norms: one thread per row
        if (tid < PREP_ROWS) {
            const float4* r = (const float4*)(src + (size_t)(rbase + tid) * DHEAD);
            float s = 0.f;
            #pragma unroll
            for (int k4 = 0; k4 < 32; k4++) {
                float4 v = __ldg(r + k4);
                s += v.x * v.x + v.y * v.y + v.z * v.z + v.w * v.w;
            }
            g_nscale[rbase + tid] = sqrtf(s) * SCALE_CONST;
        }
    } else {
        #pragma unroll
        for (int i = 0; i < 4; i++) {
            union { __half h[8]; uint4 u; } ph;
            #pragma unroll
            for (int j = 0; j < 8; j++)
                ph.h[j] = __float2half(acc[i][j]);
            int row = rbase + 4 * rg + i;
            uint32_t off = (uint32_t)(row >> 7) * 32768u
                         + (uint32_t)(col8 >> 6) * 16384u
                         + sw128((uint32_t)(row & 127) * 128u + (uint32_t)(col8 & 63) * 2u);
            *(uint4*)((char*)g_q + off) = ph.u;
        }
    }
}

// ================================================================================
// Main GEMM via mma.sync fp16. CTA: 64q x 128k per iter, G=16 k-tiles
// (grid = 4 x 64 = 256 CTAs = one clean wave at 2/SM). A fragments register-
// resident (loaded once). B fragments SOFTWARE-PIPELINED (preload ks+1 during
// MMAs of ks). B smem double-buffered via cp.async. 8 warps, warp tile 32x32.
// ================================================================================
#define G 16
#define MT3 256
#define SA   0                     // 16 KB A (two 8KB half-slabs)
#define SB   16384                 // 2 x 32 KB B
#define SNSC 81920                 // G x 512 B nscale
#define MAIN_SMEM_BYTES (SNSC + G * 512)

__device__ __forceinline__ void ldm_x4(uint32_t* r, uint32_t addr) {
    asm volatile("ldmatrix.sync.aligned.m8n8.x4.shared.b16 {%0,%1,%2,%3}, [%4];"
                 : "=r"(r[0]), "=r"(r[1]), "=r"(r[2]), "=r"(r[3])
                 : "r"(addr));
}

__device__ __forceinline__ void mma_fp16(float* d, const uint32_t* a,
                                         uint32_t b0, uint32_t b1) {
    asm volatile(
        "mma.sync.aligned.m16n8k16.row.col.f32.f16.f16.f32 "
        "{%0,%1,%2,%3}, {%4,%5,%6,%7}, {%8,%9}, {%0,%1,%2,%3};"
        : "+f"(d[0]), "+f"(d[1]), "+f"(d[2]), "+f"(d[3])
        : "r"(a[0]), "r"(a[1]), "r"(a[2]), "r"(a[3]), "r"(b0), "r"(b1));
}

__device__ __forceinline__ void cpa16(uint32_t s, const void* g) {
    asm volatile("cp.async.cg.shared.global [%0], [%1], 16;" :: "r"(s), "l"(g));
}
__device__ __forceinline__ void cpa_commit() {
    asm volatile("cp.async.commit_group;");
}

__global__ __launch_bounds__(MT3, 2)
void qjl_mma4_kernel(float* __restrict__ out)
{
    extern __shared__ char smem[];
    uint32_t sb;
    asm("{ .reg .u64 t; cvta.to.shared.u64 t, %1; cvt.u32.u64 %0, t; }"
        : "=r"(sb) : "l"(smem));

    const int tid = threadIdx.x;
    const int warp = tid >> 5, lane = tid & 31;
    const int qtile  = blockIdx.y * 64;
    const int ktile0 = blockIdx.x * (G * 128);

    // ---- group 0: A (16KB = our 64 rows of the 128-row tile, both slabs) ----
    {
        const char* gAbase = (const char*)g_q + (size_t)(qtile >> 7) * 32768
                           + (uint32_t)(qtile & 127) * 128u;
        #pragma unroll
        for (int i = tid; i < 1024; i += MT3) {
            int s = i >> 9, d = (i & 511) * 16;
            cpa16(sb + SA + s * 8192 + d, gAbase + s * 16384 + d);
        }
        cpa_commit();
    }
    // ---- group 1: B0 + all G nscale segments ----
    {
        const char* gB = (const char*)g_signs + (size_t)(ktile0 >> 7) * 32768;
        #pragma unroll
        for (int i = tid; i < 2048; i += MT3)
            cpa16(sb + SB + i * 16, gB + i * 16);
        #pragma unroll
        for (int i = tid; i < (G * 32); i += MT3)
            cpa16(sb + SNSC + i * 16, (const char*)(g_nscale + ktile0) + i * 16);
        cpa_commit();
    }

    const int wm = warp >> 2;          // 0..1  (q 32-half)
    const int wn = warp & 3;           // 0..3  (k 32-quarter)
    const int lr = lane & 15;
    const uint32_t lcB = (uint32_t)(lane >> 4) * 16u;

    // ---- wait A, load A fragments ONCE (register-resident across G) ----
    asm volatile("cp.async.wait_group 1;" ::: "memory");
    __syncthreads();

    uint32_t af[8][2][4];
    {
        const uint32_t arow = (uint32_t)(wm * 32 + lr) * 128u + lcB;
        #pragma unroll
        for (int ks = 0; ks < 8; ks++)
            #pragma unroll
            for (int i = 0; i < 2; i++)
                ldm_x4(af[ks][i],
                       sb + SA + (ks >> 2) * 8192
                          + sw128(arow + (uint32_t)i * 2048u + (uint32_t)(ks & 3) * 32u));
    }

    uint32_t brow[2];
    brow[0] = (uint32_t)(wn * 32 + lr) * 128u + lcB;
    brow[1] = brow[0] + 2048u;

    const int er0 = qtile + wm * 32 + (lane >> 2);
    const int ec0 = wn * 32 + 2 * (lane & 3);

    #pragma unroll 1
    for (int it = 0; it < G; it++) {
        const int kt = ktile0 + it * 128;
        const int buf = it & 1;

        asm volatile("cp.async.wait_group 0;" ::: "memory");
        __syncthreads();   // B[it] visible; all warps done with other buf

        if (it + 1 < G) {  // prefetch B[it+1]
            const int nb = (it + 1) & 1;
            const char* gB = (const char*)g_signs + (size_t)((kt + 128) >> 7) * 32768;
            #pragma unroll
            for (int i = tid; i < 2048; i += MT3)
                cpa16(sb + SB + nb * 32768 + i * 16, gB + i * 16);
            cpa_commit();
        }

        const uint32_t bbase = sb + SB + buf * 32768;
        const float* nscs = (const float*)(smem + SNSC + it * 512);

        float acc[2][4][4];
        #pragma unroll
        for (int i = 0; i < 2; i++)
            #pragma unroll
            for (int j = 0; j < 4; j++)
                #pragma unroll
                for (int t = 0; t < 4; t++) acc[i][j][t] = 0.f;

        // ---- software-pipelined k-loop: preload bf[ks+1] during MMAs of ks ----
        uint32_t bf[2][2][4];
        #pragma unroll
        for (int jj = 0; jj < 2; jj++)
            ldm_x4(bf[0][jj], bbase + sw128(brow[jj]));

        #pragma unroll
        for (int ks = 0; ks < 8; ks++) {
            const int cur = ks & 1;
            if (ks < 7) {
                const int kn = ks + 1;
                #pragma unroll
                for (int jj = 0; jj < 2; jj++)
                    ldm_x4(bf[cur ^ 1][jj],
                           bbase + (kn >> 2) * 16384
                                 + sw128(brow[jj] + (uint32_t)(kn & 3) * 32u));
            }
            #pragma unroll
            for (int i = 0; i < 2; i++)
                #pragma unroll
                for (int n8 = 0; n8 < 4; n8++)
                    mma_fp16(acc[i][n8], af[ks][i],
                             bf[cur][n8 >> 1][n8 & 1], bf[cur][n8 >> 1][(n8 & 1) + 2]);
        }

        // ---- epilogue: scale by nscale[col], store ----
        #pragma unroll
        for (int i = 0; i < 2; i++) {
            #pragma unroll
            for (int n8 = 0; n8 < 4; n8++) {
                int r0 = er0 + i * 16;
                int cl = ec0 + n8 * 8;
                int c = kt + cl;
                float s0 = nscs[cl], s1 = nscs[cl + 1];
                float2 v0 = make_float2(acc[i][n8][0] * s0, acc[i][n8][1] * s1);
                float2 v1 = make_float2(acc[i][n8][2] * s0, acc[i][n8][3] * s1);
                *(float2*)(out + (size_t)r0 * NK + c) = v0;
                *(float2*)(out + (size_t)(r0 + 8) * NK + c) = v1;
            }
        }
    }
}

// ================================================================================
extern "C" void kernel_launch(void* const* d_in, const int* in_sizes, int n_in,
                              void* d_out, int out_size)
{
    const float* query    = (const float*)d_in[0];
    const float* residual = (const float*)d_in[1];
    const float* S        = (const float*)d_in[2];
    float* out = (float*)d_out;

    cudaFuncSetAttribute(qjl_mma4_kernel,
                         cudaFuncAttributeMaxDynamicSharedMemorySize, MAIN_SMEM_BYTES);

    // 384 blocks, 128 threads, no smem (S is L1/L2-hot)
    qjl_prep_kernel<<<(NK + NQ) / PREP_ROWS, PREP_THREADS>>>(query, residual, S);

    // 4 k-groups x 64 q-tiles = 256 CTAs (one clean wave @ 2/SM)
    qjl_mma4_kernel<<<dim3(NK / (G * 128), NQ / 64), MT3, MAIN_SMEM_BYTES>>>(out);
}

// round 13
// speedup vs baseline: 1.2157x; 1.2157x over previous
#include <cuda_runtime.h>
#include <cuda_bf16.h>
#include <cuda_fp16.h>
#include <cstdint>

// Problem constants (fixed by the dataset)
#define DHEAD 128
#define MPROJ 128
#define NQ    4096
#define NK    8192
#define SCALE_CONST 0.009791516698f  // sqrt(pi/2)/128

// ---------------- device-global scratch (pre-swizzled SW128 slab layout) -------
// g_q / g_signs: fp16, 128-row tiles of 32KB; two 16KB slabs (64 cols each);
//                slab offset = sw128(row*128 + col*2).
__device__ __half g_signs[NK * MPROJ];
__device__ float  g_nscale[NK];
__device__ __half g_q[NQ * MPROJ];

__device__ __forceinline__ uint32_t sw128(uint32_t x) { return x ^ ((x >> 3) & 0x70); }

// ================================================================================
// Prep: fp32 GEMM rows @ S^T. Block = 32 rows x 64 cols (half of S) -> smem
// 50.7KB -> 4 CTAs/SM. 128 threads, 2 rows x 8 cols each. FMA k-order identical
// to prior passing rounds (sign decisions are boundary-sensitive; fp32 only).
//   grid.x [0,256): residual -> signs (fp16 ±1, swizzled) + nscale
//   grid.x [256,384): query  -> q_proj (fp16, swizzled)
//   grid.y: column half (0: cols 0-63, 1: cols 64-127)
// ================================================================================
#define PREP_ROWS 32
#define PREP_COLS 64
#define PREP_THREADS 128
#define PADP 132
#define PREP_SMEM_BYTES ((PREP_ROWS * PADP + PREP_COLS * PADP) * 4)

__global__ __launch_bounds__(PREP_THREADS)
void qjl_prep_kernel(const float* __restrict__ query,
                     const float* __restrict__ residual,
                     const float* __restrict__ S)
{
    extern __shared__ float smf[];
    float* Ash = smf;                       // [32][132]
    float* Ssh = smf + PREP_ROWS * PADP;    // [64][132]

    const int tid = threadIdx.x;
    const bool is_res = (blockIdx.x < (NK / PREP_ROWS));
    const int rbase = is_res ? blockIdx.x * PREP_ROWS
                             : (blockIdx.x - NK / PREP_ROWS) * PREP_ROWS;
    const int colbase = blockIdx.y * PREP_COLS;
    const float* src = is_res ? residual : query;

    const float4* gA = (const float4*)(src + (size_t)rbase * DHEAD);
    #pragma unroll
    for (int idx = tid; idx < PREP_ROWS * 32; idx += PREP_THREADS) {
        int r = idx >> 5, c4 = idx & 31;
        *(float4*)(Ash + r * PADP + c4 * 4) = gA[idx];
    }
    const float4* gS = (const float4*)(S + (size_t)colbase * DHEAD);
    #pragma unroll
    for (int idx = tid; idx < PREP_COLS * 32; idx += PREP_THREADS) {
        int r = idx >> 5, c4 = idx & 31;
        *(float4*)(Ssh + r * PADP + c4 * 4) = gS[idx];
    }
    __syncthreads();

    // norms: once per row (col-half 0 only)
    if (is_res && blockIdx.y == 0 && tid < PREP_ROWS) {
        float s = 0.f;
        #pragma unroll
        for (int k4 = 0; k4 < 32; k4++) {
            float4 a = *(const float4*)(Ash + tid * PADP + k4 * 4);
            s += a.x * a.x + a.y * a.y + a.z * a.z + a.w * a.w;
        }
        g_nscale[rbase + tid] = sqrtf(s) * SCALE_CONST;
    }

    const int rg = tid & 15;   // 2 rows per thread
    const int cg = tid >> 4;   // 8 cols per thread (0..7 within 64)

    float acc[2][8];
    #pragma unroll
    for (int i = 0; i < 2; i++)
        #pragma unroll
        for (int j = 0; j < 8; j++) acc[i][j] = 0.f;

    const float* arow0 = Ash + (2 * rg) * PADP;
    const float* arow1 = Ash + (2 * rg + 1) * PADP;
    const float* brows = Ssh + (8 * cg) * PADP;

    #pragma unroll 8
    for (int k4 = 0; k4 < 32; k4++) {
        float4 a0 = *(const float4*)(arow0 + k4 * 4);
        float4 a1 = *(const float4*)(arow1 + k4 * 4);
        #pragma unroll
        for (int j = 0; j < 8; j++) {
            float4 b = *(const float4*)(brows + j * PADP + k4 * 4);
            acc[0][j] = fmaf(a0.x, b.x, acc[0][j]);
            acc[0][j] = fmaf(a0.y, b.y, acc[0][j]);
            acc[0][j] = fmaf(a0.z, b.z, acc[0][j]);
            acc[0][j] = fmaf(a0.w, b.w, acc[0][j]);
            acc[1][j] = fmaf(a1.x, b.x, acc[1][j]);
            acc[1][j] = fmaf(a1.y, b.y, acc[1][j]);
            acc[1][j] = fmaf(a1.z, b.z, acc[1][j]);
            acc[1][j] = fmaf(a1.w, b.w, acc[1][j]);
        }
    }

    const int col8 = colbase + 8 * cg;     // global col base (0..120)
    if (is_res) {
        #pragma unroll
        for (int i = 0; i < 2; i++) {
            union { __half h[8]; uint4 u; } pk;
            #pragma unroll
            for (int j = 0; j < 8; j++)
                pk.h[j] = __float2half(acc[i][j] >= 0.f ? 1.f : -1.f);
            int row = rbase + 2 * rg + i;
            uint32_t off = (uint32_t)(row >> 7) * 32768u
                         + (uint32_t)(col8 >> 6) * 16384u
                         + sw128((uint32_t)(row & 127) * 128u + (uint32_t)(col8 & 63) * 2u);
            *(uint4*)((char*)g_signs + off) = pk.u;
        }
    } else {
        #pragma unroll
        for (int i = 0; i < 2; i++) {
            union { __half h[8]; uint4 u; } ph;
            #pragma unroll
            for (int j = 0; j < 8; j++)
                ph.h[j] = __float2half(acc[i][j]);
            int row = rbase + 2 * rg + i;
            uint32_t off = (uint32_t)(row >> 7) * 32768u
                         + (uint32_t)(col8 >> 6) * 16384u
                         + sw128((uint32_t)(row & 127) * 128u + (uint32_t)(col8 & 63) * 2u);
            *(uint4*)((char*)g_q + off) = ph.u;
        }
    }
}

// ================================================================================
// Main GEMM via mma.sync fp16 (R11 verbatim — best measured: 45.0us).
// CTA: 64q x 128k per iter, G=8 k-tiles. A fragments register-resident.
// B double-buffered cp.async. 8 warps, warp tile 32x32, SW128 smem.
// ================================================================================
#define G 8
#define MT3 256
#define SA   0                     // 16 KB A (two 8KB half-slabs)
#define SB   16384                 // 2 x 32 KB B
#define SNSC 81920                 // G x 512 B nscale
#define MAIN_SMEM_BYTES (SNSC + G * 512)

__device__ __forceinline__ void ldm_x4(uint32_t* r, uint32_t addr) {
    asm volatile("ldmatrix.sync.aligned.m8n8.x4.shared.b16 {%0,%1,%2,%3}, [%4];"
                 : "=r"(r[0]), "=r"(r[1]), "=r"(r[2]), "=r"(r[3])
                 : "r"(addr));
}

__device__ __forceinline__ void mma_fp16(float* d, const uint32_t* a,
                                         uint32_t b0, uint32_t b1) {
    asm volatile(
        "mma.sync.aligned.m16n8k16.row.col.f32.f16.f16.f32 "
        "{%0,%1,%2,%3}, {%4,%5,%6,%7}, {%8,%9}, {%0,%1,%2,%3};"
        : "+f"(d[0]), "+f"(d[1]), "+f"(d[2]), "+f"(d[3])
        : "r"(a[0]), "r"(a[1]), "r"(a[2]), "r"(a[3]), "r"(b0), "r"(b1));
}

__device__ __forceinline__ void cpa16(uint32_t s, const void* g) {
    asm volatile("cp.async.cg.shared.global [%0], [%1], 16;" :: "r"(s), "l"(g));
}
__device__ __forceinline__ void cpa_commit() {
    asm volatile("cp.async.commit_group;");
}

__global__ __launch_bounds__(MT3, 2)
void qjl_mma3_kernel(float* __restrict__ out)
{
    extern __shared__ char smem[];
    uint32_t sb;
    asm("{ .reg .u64 t; cvta.to.shared.u64 t, %1; cvt.u32.u64 %0, t; }"
        : "=r"(sb) : "l"(smem));

    const int tid = threadIdx.x;
    const int warp = tid >> 5, lane = tid & 31;
    const int qtile  = blockIdx.y * 64;
    const int ktile0 = blockIdx.x * (G * 128);

    // ---- group 0: A (16KB = our 64 rows of the 128-row tile, both slabs) ----
    {
        const char* gAbase = (const char*)g_q + (size_t)(qtile >> 7) * 32768
                           + (uint32_t)(qtile & 127) * 128u;
        #pragma unroll
        for (int i = tid; i < 1024; i += MT3) {
            int s = i >> 9, d = (i & 511) * 16;
            cpa16(sb + SA + s * 8192 + d, gAbase + s * 16384 + d);
        }
        cpa_commit();
    }
    // ---- group 1: B0 + all G nscale segments ----
    {
        const char* gB = (const char*)g_signs + (size_t)(ktile0 >> 7) * 32768;
        #pragma unroll
        for (int i = tid; i < 2048; i += MT3)
            cpa16(sb + SB + i * 16, gB + i * 16);
        cpa16(sb + SNSC + tid * 16, (const char*)(g_nscale + ktile0) + tid * 16);
        cpa_commit();
    }

    const int wm = warp >> 2;          // 0..1  (q 32-half)
    const int wn = warp & 3;           // 0..3  (k 32-quarter)
    const int lr = lane & 15;
    const uint32_t lcB = (uint32_t)(lane >> 4) * 16u;

    // ---- wait A, load A fragments ONCE (register-resident across G) ----
    asm volatile("cp.async.wait_group 1;" ::: "memory");
    __syncthreads();

    uint32_t af[8][2][4];
    {
        const uint32_t arow = (uint32_t)(wm * 32 + lr) * 128u + lcB;
        #pragma unroll
        for (int ks = 0; ks < 8; ks++)
            #pragma unroll
            for (int i = 0; i < 2; i++)
                ldm_x4(af[ks][i],
                       sb + SA + (ks >> 2) * 8192
                          + sw128(arow + (uint32_t)i * 2048u + (uint32_t)(ks & 3) * 32u));
    }

    uint32_t brow[2];
    brow[0] = (uint32_t)(wn * 32 + lr) * 128u + lcB;
    brow[1] = brow[0] + 2048u;

    const int er0 = qtile + wm * 32 + (lane >> 2);
    const int ec0 = wn * 32 + 2 * (lane & 3);

    #pragma unroll 1
    for (int it = 0; it < G; it++) {
        const int kt = ktile0 + it * 128;
        const int buf = it & 1;

        asm volatile("cp.async.wait_group 0;" ::: "memory");
        __syncthreads();   // B[it] visible; all warps done with other buf

        if (it + 1 < G) {  // prefetch B[it+1]
            const int nb = (it + 1) & 1;
            const char* gB = (const char*)g_signs + (size_t)((kt + 128) >> 7) * 32768;
            #pragma unroll
            for (int i = tid; i < 2048; i += MT3)
                cpa16(sb + SB + nb * 32768 + i * 16, gB + i * 16);
            cpa_commit();
        }

        const uint32_t bbase = sb + SB + buf * 32768;
        const float* nscs = (const float*)(smem + SNSC + it * 512);

        float acc[2][4][4];
        #pragma unroll
        for (int i = 0; i < 2; i++)
            #pragma unroll
            for (int j = 0; j < 4; j++)
                #pragma unroll
                for (int t = 0; t < 4; t++) acc[i][j][t] = 0.f;

        #pragma unroll
        for (int ks = 0; ks < 8; ks++) {
            uint32_t bf[2][4];
            #pragma unroll
            for (int jj = 0; jj < 2; jj++)
                ldm_x4(bf[jj], bbase + (ks >> 2) * 16384
                             + sw128(brow[jj] + (uint32_t)(ks & 3) * 32u));
            #pragma unroll
            for (int i = 0; i < 2; i++)
                #pragma unroll
                for (int n8 = 0; n8 < 4; n8++)
                    mma_fp16(acc[i][n8], af[ks][i],
                             bf[n8 >> 1][n8 & 1], bf[n8 >> 1][(n8 & 1) + 2]);
        }

        // ---- epilogue: scale by nscale[col], store ----
        #pragma unroll
        for (int i = 0; i < 2; i++) {
            #pragma unroll
            for (int n8 = 0; n8 < 4; n8++) {
                int r0 = er0 + i * 16;
                int cl = ec0 + n8 * 8;
                int c = kt + cl;
                float s0 = nscs[cl], s1 = nscs[cl + 1];
                float2 v0 = make_float2(acc[i][n8][0] * s0, acc[i][n8][1] * s1);
                float2 v1 = make_float2(acc[i][n8][2] * s0, acc[i][n8][3] * s1);
                *(float2*)(out + (size_t)r0 * NK + c) = v0;
                *(float2*)(out + (size_t)(r0 + 8) * NK + c) = v1;
            }
        }
    }
}

// ================================================================================
extern "C" void kernel_launch(void* const* d_in, const int* in_sizes, int n_in,
                              void* d_out, int out_size)
{
    const float* query    = (const float*)d_in[0];
    const float* residual = (const float*)d_in[1];
    const float* S        = (const float*)d_in[2];
    float* out = (float*)d_out;

    cudaFuncSetAttribute(qjl_prep_kernel,
                         cudaFuncAttributeMaxDynamicSharedMemorySize, PREP_SMEM_BYTES);
    cudaFuncSetAttribute(qjl_mma3_kernel,
                         cudaFuncAttributeMaxDynamicSharedMemorySize, MAIN_SMEM_BYTES);

    // 384 row-blocks x 2 col-halves = 768 blocks, 128 threads, 4 CTAs/SM
    qjl_prep_kernel<<<dim3((NK + NQ) / PREP_ROWS, 2), PREP_THREADS,
                      PREP_SMEM_BYTES>>>(query, residual, S);

    // 8 k-groups x 64 q-tiles = 512 CTAs (2/SM)
    qjl_mma3_kernel<<<dim3(NK / (G * 128), NQ / 64), MT3, MAIN_SMEM_BYTES>>>(out);
}